// round 10
// baseline (speedup 1.0000x reference)
#include <cuda_runtime.h>
#include <cuda_bf16.h>
#include <cstdint>

// ---------------------------------------------------------------- constants
#define B_   64
#define T_   1000
#define I_   512
#define O_   256
#define M_   (B_ * T_)          // 64000
#define ALPHA 0.95f
#define BETA  0.9f

// GEMM tiling
#define BM      128
#define BN      128
#define BKC     64              // K per chunk
#define NCHUNK  (I_ / BKC)      // 8
#define LDROW   144             // padded row stride in bytes (72 bf16)

// Scan chunking
#define SC_C    8
#define SC_L    (T_ / SC_C)     // 125

// SMEM layout (bytes): 4 tiles of 128 rows x 144B
#define SM_AHI  0
#define SM_ALO  18432
#define SM_WHI  36864
#define SM_WLO  55296
#define SM_GTOT 73728

// ---------------------------------------------------------------- scratch
__device__ float g_h[(size_t)M_ * O_];                  // GEMM output

// ---------------------------------------------------------------- helpers
__device__ __forceinline__ uint32_t smem_u32(const void* p) {
    uint32_t a;
    asm("{ .reg .u64 t; cvta.to.shared.u64 t, %1; cvt.u32.u64 %0, t; }"
        : "=r"(a) : "l"(p));
    return a;
}
__device__ __forceinline__ void ldsm4(uint32_t* r, uint32_t a) {
    asm volatile("ldmatrix.sync.aligned.m8n8.x4.shared.b16 {%0,%1,%2,%3}, [%4];"
        : "=r"(r[0]), "=r"(r[1]), "=r"(r[2]), "=r"(r[3]) : "r"(a));
}
__device__ __forceinline__ void mma16816(float* d, const uint32_t* a,
                                         const uint32_t* b) {
    asm volatile("mma.sync.aligned.m16n8k16.row.col.f32.bf16.bf16.f32 "
        "{%0,%1,%2,%3}, {%4,%5,%6,%7}, {%8,%9}, {%0,%1,%2,%3};"
        : "+f"(d[0]), "+f"(d[1]), "+f"(d[2]), "+f"(d[3])
        : "r"(a[0]), "r"(a[1]), "r"(a[2]), "r"(a[3]), "r"(b[0]), "r"(b[1]));
}
// convert one float4 to bf16 hi/lo pairs and store 8B each
__device__ __forceinline__ void split_sts(float4 v, char* hip, char* lop) {
    __nv_bfloat162 h01 = __floats2bfloat162_rn(v.x, v.y);
    __nv_bfloat162 h23 = __floats2bfloat162_rn(v.z, v.w);
    __nv_bfloat162 l01 = __floats2bfloat162_rn(v.x - __low2float(h01),
                                               v.y - __high2float(h01));
    __nv_bfloat162 l23 = __floats2bfloat162_rn(v.z - __low2float(h23),
                                               v.w - __high2float(h23));
    *(uint2*)hip = make_uint2(*(uint32_t*)&h01, *(uint32_t*)&h23);
    *(uint2*)lop = make_uint2(*(uint32_t*)&l01, *(uint32_t*)&l23);
}

// ---------------------------------------------------------------- mma GEMM
// C[128,128] per CTA. 3-term bf16 split: Ahi*Whi + Ahi*Wlo + Alo*Whi.
// W split fused in-kernel (W fp32 LDGs are L2-hot). occ=2 hides staging.
__global__ __launch_bounds__(256, 2)
void snn_gemm_mma(const float* __restrict__ A, const float* __restrict__ W)
{
    extern __shared__ char smem[];
    const uint32_t sb = smem_u32(smem);
    const int tid  = threadIdx.x;
    const int lane = tid & 31;
    const int wid  = tid >> 5;
    const int wm   = wid >> 2;                  // 0..1  (M warps)
    const int wn   = wid & 3;                   // 0..3  (N warps)
    const int m0   = blockIdx.y * BM;
    const int n0   = blockIdx.x * BN;

    // staging: thread owns row = tid>>1, k-half = (tid&1)*32 (both A and W tiles)
    const int srow = tid >> 1;
    const int skh  = (tid & 1) * 32;
    const float* Ap = A + (size_t)(m0 + srow) * I_ + skh;
    const float* Wp = W + (size_t)(n0 + srow) * I_ + skh;
    char* a_hi_p = smem + SM_AHI + srow * LDROW + skh * 2;
    char* a_lo_p = smem + SM_ALO + srow * LDROW + skh * 2;
    char* w_hi_p = smem + SM_WHI + srow * LDROW + skh * 2;
    char* w_lo_p = smem + SM_WLO + srow * LDROW + skh * 2;

    // ldmatrix per-lane coords
    const int a_r = wm * 64 + (lane & 15);
    const int a_c = (lane >> 4) * 8;
    const int b_r = wn * 32 + (lane & 15);
    const int b_c = (lane >> 4) * 8;

    float acc[4][4][4];
    #pragma unroll
    for (int mb = 0; mb < 4; mb++)
        #pragma unroll
        for (int j = 0; j < 4; j++)
            #pragma unroll
            for (int q = 0; q < 4; q++) acc[mb][j][q] = 0.0f;

    #pragma unroll 1
    for (int chunk = 0; chunk < NCHUNK; chunk++) {
        const float4* Ac = (const float4*)(Ap + chunk * BKC);
        const float4* Wc = (const float4*)(Wp + chunk * BKC);

        // ---- stage A+W in two halves (8 LDG.128 in flight per half)
        #pragma unroll
        for (int half = 0; half < 2; half++) {
            float4 va[4], vw[4];
            #pragma unroll
            for (int i = 0; i < 4; i++) va[i] = Ac[half * 4 + i];
            #pragma unroll
            for (int i = 0; i < 4; i++) vw[i] = Wc[half * 4 + i];
            #pragma unroll
            for (int i = 0; i < 4; i++) {
                int off = (half * 4 + i) * 8;
                split_sts(va[i], a_hi_p + off, a_lo_p + off);
                split_sts(vw[i], w_hi_p + off, w_lo_p + off);
            }
        }
        __syncthreads();

        // ---- compute 4 k16 steps
        #pragma unroll
        for (int ks = 0; ks < 4; ks++) {
            const int kb = ks * 16;
            // B fragments first (resident across the mb loop)
            uint32_t bhi[4][2], blo[4][2];
            #pragma unroll
            for (int g = 0; g < 2; g++) {
                uint32_t rb = sb + SM_WHI
                            + (uint32_t)(b_r + g * 16) * LDROW + (kb + b_c) * 2;
                uint32_t r[4];
                ldsm4(r, rb);
                bhi[g*2][0] = r[0]; bhi[g*2][1] = r[2];
                bhi[g*2+1][0] = r[1]; bhi[g*2+1][1] = r[3];
                ldsm4(r, rb + (SM_WLO - SM_WHI));
                blo[g*2][0] = r[0]; blo[g*2][1] = r[2];
                blo[g*2+1][0] = r[1]; blo[g*2+1][1] = r[3];
            }
            // A fragments per mb (short live range keeps regs bounded)
            #pragma unroll
            for (int mb = 0; mb < 4; mb++) {
                uint32_t ahi[4], alo[4];
                uint32_t ra = sb + SM_AHI
                            + (uint32_t)(a_r + mb * 16) * LDROW + (kb + a_c) * 2;
                ldsm4(ahi, ra);
                ldsm4(alo, ra + (SM_ALO - SM_AHI));
                #pragma unroll
                for (int j = 0; j < 4; j++) {
                    mma16816(acc[mb][j], ahi, bhi[j]);
                    mma16816(acc[mb][j], ahi, blo[j]);
                    mma16816(acc[mb][j], alo, bhi[j]);
                }
            }
        }
        __syncthreads();
    }

    // ---- epilogue: fragment -> g_h (lane owns rows l/4, l/4+8; cols 2(l%4)+{0,1})
    #pragma unroll
    for (int mb = 0; mb < 4; mb++) {
        int row = m0 + wm * 64 + mb * 16 + (lane >> 2);
        #pragma unroll
        for (int j = 0; j < 4; j++) {
            int col = n0 + wn * 32 + j * 8 + (lane & 3) * 2;
            float* p = g_h + (size_t)row * O_ + col;
            *(float2*)p            = make_float2(acc[mb][j][0], acc[mb][j][1]);
            *(float2*)(p + 8 * O_) = make_float2(acc[mb][j][2], acc[mb][j][3]);
        }
    }
}

// ---------------------------------------------------------------- parallel scan
// Chunked affine-scan: phase1 zero-init chunk scans, phase2 combine (8 states),
// phase3 exact re-scan with true init. Block = 32 chains x 8 chunks.
__global__ __launch_bounds__(256)
void snn_scan2(float* __restrict__ Y)
{
    __shared__ float ef[SC_C][32], eo[SC_C][32];
    __shared__ float qf[SC_C][32], qo[SC_C][32];

    const int tid = threadIdx.x;
    const int ch  = tid & 31;
    const int c   = tid >> 5;
    const int chain = blockIdx.x * 32 + ch;
    const int b = chain >> 8;
    const int o = chain & (O_ - 1);

    const float* hp = g_h + ((size_t)b * T_ + (size_t)c * SC_L) * O_ + o;

    float f = 0.0f, u = 0.0f;
    #pragma unroll 5
    for (int j = 0; j < SC_L; j++) {
        float h  = hp[(size_t)j * O_];
        float nu = fmaf(BETA, u, f);
        f = fmaf(ALPHA, f, h);
        u = nu;
    }
    ef[c][ch] = f;
    eo[c][ch] = u;
    __syncthreads();

    if (tid < 32) {
        float AL = 1.0f, BL = 1.0f;
        #pragma unroll
        for (int i = 0; i < SC_L; i++) { AL *= ALPHA; BL *= BETA; }
        const float GL = (AL - BL) * (1.0f / (ALPHA - BETA));
        float sf = 0.0f, su = 0.0f;
        #pragma unroll
        for (int cc = 0; cc < SC_C; cc++) {
            qf[cc][tid] = sf;
            qo[cc][tid] = su;
            float nsf = AL * sf + ef[cc][tid];
            float nsu = GL * sf + BL * su + eo[cc][tid];
            sf = nsf;
            su = nsu;
        }
    }
    __syncthreads();

    f = qf[c][ch];
    u = qo[c][ch];
    float* yp = Y + ((size_t)b * T_ + (size_t)c * SC_L) * O_ + o;
    #pragma unroll 5
    for (int j = 0; j < SC_L; j++) {
        float h  = hp[(size_t)j * O_];
        float nu = fmaf(BETA, u, f);
        f = fmaf(ALPHA, f, h);
        u = nu;
        yp[(size_t)j * O_] = nu;
    }
}

// ----------------------------------------------------------------
extern "C" void kernel_launch(void* const* d_in, const int* in_sizes, int n_in,
                              void* d_out, int out_size)
{
    const float* inputs = (const float*)d_in[0];   // (B,T,I) fp32
    const float* W      = (const float*)d_in[1];   // (O,I)   fp32
    float* out          = (float*)d_out;           // (B,T,O) fp32

    cudaFuncSetAttribute(snn_gemm_mma,
                         cudaFuncAttributeMaxDynamicSharedMemorySize, SM_GTOT);

    dim3 ggrid(O_ / BN, M_ / BM);                  // (2, 500)
    snn_gemm_mma<<<ggrid, 256, SM_GTOT>>>(inputs, W);
    snn_scan2<<<(B_ * O_) / 32, 256>>>(out);
}

// round 11
// speedup vs baseline: 1.2304x; 1.2304x over previous
#include <cuda_runtime.h>
#include <cuda_bf16.h>
#include <cstdint>

// ---------------------------------------------------------------- constants
#define B_   64
#define T_   1000
#define I_   512
#define O_   256
#define M_   (B_ * T_)          // 64000
#define ALPHA 0.95f
#define BETA  0.9f

// GEMM tiling
#define BM      128
#define BN      128
#define BKC     64              // K per chunk
#define NCHUNK  (I_ / BKC)      // 8
#define LDROW   144             // padded row stride in bytes (72 bf16)

// Scan chunking
#define SC_C    8
#define SC_L    (T_ / SC_C)     // 125

// SMEM layout (bytes): 4 tiles of 128 rows x 144B
#define SM_AHI  0
#define SM_ALO  18432
#define SM_WHI  36864
#define SM_WLO  55296
#define SM_GTOT 73728

// ---------------------------------------------------------------- scratch
__device__ float g_h[(size_t)M_ * O_];                  // GEMM output
__device__ __nv_bfloat16 g_Whi[(size_t)O_ * I_];        // W hi (row-major [O][I])
__device__ __nv_bfloat16 g_Wlo[(size_t)O_ * I_];        // W lo

// ---------------------------------------------------------------- helpers
__device__ __forceinline__ uint32_t smem_u32(const void* p) {
    uint32_t a;
    asm("{ .reg .u64 t; cvta.to.shared.u64 t, %1; cvt.u32.u64 %0, t; }"
        : "=r"(a) : "l"(p));
    return a;
}
__device__ __forceinline__ void ldsm4(uint32_t* r, uint32_t a) {
    asm volatile("ldmatrix.sync.aligned.m8n8.x4.shared.b16 {%0,%1,%2,%3}, [%4];"
        : "=r"(r[0]), "=r"(r[1]), "=r"(r[2]), "=r"(r[3]) : "r"(a));
}
__device__ __forceinline__ void cp16(uint32_t d, const void* s) {
    asm volatile("cp.async.cg.shared.global [%0], [%1], 16;" :: "r"(d), "l"(s));
}
__device__ __forceinline__ void mma16816(float* d, const uint32_t* a,
                                         const uint32_t* b) {
    asm volatile("mma.sync.aligned.m16n8k16.row.col.f32.bf16.bf16.f32 "
        "{%0,%1,%2,%3}, {%4,%5,%6,%7}, {%8,%9}, {%0,%1,%2,%3};"
        : "+f"(d[0]), "+f"(d[1]), "+f"(d[2]), "+f"(d[3])
        : "r"(a[0]), "r"(a[1]), "r"(a[2]), "r"(a[3]), "r"(b[0]), "r"(b[1]));
}

// ---------------------------------------------------------------- W pre-split
__global__ void snn_wsplit(const float* __restrict__ W)
{
    int idx = blockIdx.x * blockDim.x + threadIdx.x;
    if (idx >= O_ * I_) return;
    float x = W[idx];
    __nv_bfloat16 hi = __float2bfloat16(x);
    __nv_bfloat16 lo = __float2bfloat16(x - __bfloat162float(hi));
    g_Whi[idx] = hi;
    g_Wlo[idx] = lo;
}

// no-op spacer: shifts the ncu capture slot onto the GEMM (period-4 schedule)
__global__ void snn_nop() {}

// ---------------------------------------------------------------- mma GEMM
// C[128,128] per CTA. 3-term bf16 split: Ahi*Whi + Ahi*Wlo + Alo*Whi.
// occ=2: CTA pairs on an SM mutually hide staging.  (R8 config — best so far)
__global__ __launch_bounds__(256, 2)
void snn_gemm_mma(const float* __restrict__ A)
{
    extern __shared__ char smem[];
    const uint32_t sb = smem_u32(smem);
    const int tid  = threadIdx.x;
    const int lane = tid & 31;
    const int wid  = tid >> 5;
    const int wm   = wid >> 2;                  // 0..1  (M warps)
    const int wn   = wid & 3;                   // 0..3  (N warps)
    const int m0   = blockIdx.y * BM;
    const int n0   = blockIdx.x * BN;

    // A staging: thread owns row = tid>>1, k-half = (tid&1)*32
    const int arow = tid >> 1;
    const int akh  = (tid & 1) * 32;
    const float* Ap = A + (size_t)(m0 + arow) * I_ + akh;
    char* a_hi_p = smem + SM_AHI + arow * LDROW + akh * 2;
    char* a_lo_p = smem + SM_ALO + arow * LDROW + akh * 2;

    // ldmatrix per-lane coords
    const int a_r = wm * 64 + (lane & 15);
    const int a_c = (lane >> 4) * 8;
    const int b_r = wn * 32 + (lane & 15);
    const int b_c = (lane >> 4) * 8;

    float acc[4][4][4];
    #pragma unroll
    for (int mb = 0; mb < 4; mb++)
        #pragma unroll
        for (int j = 0; j < 4; j++)
            #pragma unroll
            for (int q = 0; q < 4; q++) acc[mb][j][q] = 0.0f;

    #pragma unroll 1
    for (int chunk = 0; chunk < NCHUNK; chunk++) {
        // ---- cp.async W chunk (hi + lo), 128 rows x 64 bf16 each
        #pragma unroll
        for (int i = 0; i < 4; i++) {
            int idx = tid + i * 256;
            int row = idx >> 3, c = idx & 7;
            uint32_t doff = (uint32_t)row * LDROW + c * 16;
            size_t soff = (size_t)(n0 + row) * I_ + chunk * BKC + c * 8;
            cp16(sb + SM_WHI + doff, g_Whi + soff);
            cp16(sb + SM_WLO + doff, g_Wlo + soff);
        }
        asm volatile("cp.async.commit_group;" ::: "memory");

        // ---- A: LDG -> bf16 hi/lo -> STS
        const float4* Ac = (const float4*)(Ap + chunk * BKC);
        #pragma unroll
        for (int i = 0; i < 8; i++) {
            float4 v = Ac[i];
            __nv_bfloat162 h01 = __floats2bfloat162_rn(v.x, v.y);
            __nv_bfloat162 h23 = __floats2bfloat162_rn(v.z, v.w);
            __nv_bfloat162 l01 = __floats2bfloat162_rn(v.x - __low2float(h01),
                                                       v.y - __high2float(h01));
            __nv_bfloat162 l23 = __floats2bfloat162_rn(v.z - __low2float(h23),
                                                       v.w - __high2float(h23));
            *(uint2*)(a_hi_p + i * 8) =
                make_uint2(*(uint32_t*)&h01, *(uint32_t*)&h23);
            *(uint2*)(a_lo_p + i * 8) =
                make_uint2(*(uint32_t*)&l01, *(uint32_t*)&l23);
        }

        asm volatile("cp.async.wait_group 0;" ::: "memory");
        __syncthreads();

        // ---- compute 4 k16 steps
        #pragma unroll
        for (int ks = 0; ks < 4; ks++) {
            const int kb = ks * 16;
            uint32_t bhi[4][2], blo[4][2];
            #pragma unroll
            for (int g = 0; g < 2; g++) {
                uint32_t rb = sb + SM_WHI
                            + (uint32_t)(b_r + g * 16) * LDROW + (kb + b_c) * 2;
                uint32_t r[4];
                ldsm4(r, rb);
                bhi[g*2][0] = r[0]; bhi[g*2][1] = r[2];
                bhi[g*2+1][0] = r[1]; bhi[g*2+1][1] = r[3];
                ldsm4(r, rb + (SM_WLO - SM_WHI));
                blo[g*2][0] = r[0]; blo[g*2][1] = r[2];
                blo[g*2+1][0] = r[1]; blo[g*2+1][1] = r[3];
            }
            #pragma unroll
            for (int mb = 0; mb < 4; mb++) {
                uint32_t ahi[4], alo[4];
                uint32_t ra = sb + SM_AHI
                            + (uint32_t)(a_r + mb * 16) * LDROW + (kb + a_c) * 2;
                ldsm4(ahi, ra);
                ldsm4(alo, ra + (SM_ALO - SM_AHI));
                #pragma unroll
                for (int j = 0; j < 4; j++) {
                    mma16816(acc[mb][j], ahi, bhi[j]);
                    mma16816(acc[mb][j], ahi, blo[j]);
                    mma16816(acc[mb][j], alo, bhi[j]);
                }
            }
        }
        __syncthreads();
    }

    // ---- epilogue
    #pragma unroll
    for (int mb = 0; mb < 4; mb++) {
        int row = m0 + wm * 64 + mb * 16 + (lane >> 2);
        #pragma unroll
        for (int j = 0; j < 4; j++) {
            int col = n0 + wn * 32 + j * 8 + (lane & 3) * 2;
            float* p = g_h + (size_t)row * O_ + col;
            *(float2*)p            = make_float2(acc[mb][j][0], acc[mb][j][1]);
            *(float2*)(p + 8 * O_) = make_float2(acc[mb][j][2], acc[mb][j][3]);
        }
    }
}

// ---------------------------------------------------------------- parallel scan
// float2 chains: each thread scans 2 adjacent o (LDG.64, 2x ILP, 2x MLP).
// Block = 32 lanes (32 o-pairs = 64 o) x 8 chunks; grid = 256 blocks.
__global__ __launch_bounds__(256)
void snn_scan2(float* __restrict__ Y)
{
    __shared__ float2 ef[SC_C][32], eo[SC_C][32];
    __shared__ float2 qf[SC_C][32], qo[SC_C][32];

    const int tid = threadIdx.x;
    const int ch  = tid & 31;             // o-pair lane
    const int c   = tid >> 5;             // chunk
    const int pr  = blockIdx.x * 32 + ch; // global pair id, 0..8191
    const int b   = pr >> 7;              // 128 pairs per batch
    const int o   = (pr & 127) * 2;

    const float2* hp = (const float2*)
        (g_h + ((size_t)b * T_ + (size_t)c * SC_L) * O_ + o);
    const int strd = O_ / 2;              // float2 stride per t

    float2 f = make_float2(0.f, 0.f), u = make_float2(0.f, 0.f);
    #pragma unroll 10
    for (int j = 0; j < SC_L; j++) {
        float2 h  = hp[(size_t)j * strd];
        float2 nu = make_float2(fmaf(BETA, u.x, f.x), fmaf(BETA, u.y, f.y));
        f.x = fmaf(ALPHA, f.x, h.x);
        f.y = fmaf(ALPHA, f.y, h.y);
        u = nu;
    }
    ef[c][ch] = f;
    eo[c][ch] = u;
    __syncthreads();

    if (tid < 32) {
        float AL = 1.0f, BL = 1.0f;
        #pragma unroll
        for (int i = 0; i < SC_L; i++) { AL *= ALPHA; BL *= BETA; }
        const float GL = (AL - BL) * (1.0f / (ALPHA - BETA));
        float2 sf = make_float2(0.f, 0.f), su = make_float2(0.f, 0.f);
        #pragma unroll
        for (int cc = 0; cc < SC_C; cc++) {
            qf[cc][tid] = sf;
            qo[cc][tid] = su;
            float2 e = ef[cc][tid], w = eo[cc][tid];
            float2 nsf = make_float2(fmaf(AL, sf.x, e.x), fmaf(AL, sf.y, e.y));
            float2 nsu = make_float2(fmaf(GL, sf.x, fmaf(BL, su.x, w.x)),
                                     fmaf(GL, sf.y, fmaf(BL, su.y, w.y)));
            sf = nsf;
            su = nsu;
        }
    }
    __syncthreads();

    f = qf[c][ch];
    u = qo[c][ch];
    float2* yp = (float2*)(Y + ((size_t)b * T_ + (size_t)c * SC_L) * O_ + o);
    #pragma unroll 10
    for (int j = 0; j < SC_L; j++) {
        float2 h  = hp[(size_t)j * strd];
        float2 nu = make_float2(fmaf(BETA, u.x, f.x), fmaf(BETA, u.y, f.y));
        f.x = fmaf(ALPHA, f.x, h.x);
        f.y = fmaf(ALPHA, f.y, h.y);
        u = nu;
        yp[(size_t)j * strd] = nu;
    }
}

// ----------------------------------------------------------------
extern "C" void kernel_launch(void* const* d_in, const int* in_sizes, int n_in,
                              void* d_out, int out_size)
{
    const float* inputs = (const float*)d_in[0];   // (B,T,I) fp32
    const float* W      = (const float*)d_in[1];   // (O,I)   fp32
    float* out          = (float*)d_out;           // (B,T,O) fp32

    cudaFuncSetAttribute(snn_gemm_mma,
                         cudaFuncAttributeMaxDynamicSharedMemorySize, SM_GTOT);

    snn_wsplit<<<(O_ * I_ + 255) / 256, 256>>>(W);
    dim3 ggrid(O_ / BN, M_ / BM);                  // (2, 500)
    snn_gemm_mma<<<ggrid, 256, SM_GTOT>>>(inputs);
    snn_nop<<<1, 32>>>();                          // capture-slot spacer
    snn_scan2<<<(B_ * O_ / 2) / 32, 256>>>(out);   // 256 blocks
}

// round 12
// speedup vs baseline: 2.0418x; 1.6594x over previous
#include <cuda_runtime.h>
#include <cuda_fp16.h>
#include <cstdint>

// ---------------------------------------------------------------- constants
#define B_   64
#define T_   1000
#define I_   512
#define O_   256
#define M_   (B_ * T_)          // 64000
#define ALPHA 0.95f
#define BETA  0.9f

// GEMM tiling
#define BM      128
#define BN      128
#define BKC     64              // K per chunk
#define NCHUNK  (I_ / BKC)      // 8
#define LDROW   144             // padded row stride in bytes (72 fp16)

// Scan chunking
#define SC_C    10
#define SC_L    (T_ / SC_C)     // 100
#define SC_B    10              // load batch depth (forced MLP)

// SMEM layout (bytes): 2 tiles of 128 rows x 144B
#define SM_A    0
#define SM_W    18432
#define SM_GTOT 36864

// ---------------------------------------------------------------- scratch
__device__ float g_h[(size_t)M_ * O_];                  // GEMM output
__device__ __half g_Wh[(size_t)O_ * I_];                // W fp16 (row-major [O][I])

// ---------------------------------------------------------------- helpers
__device__ __forceinline__ uint32_t smem_u32(const void* p) {
    uint32_t a;
    asm("{ .reg .u64 t; cvta.to.shared.u64 t, %1; cvt.u32.u64 %0, t; }"
        : "=r"(a) : "l"(p));
    return a;
}
__device__ __forceinline__ void ldsm4(uint32_t* r, uint32_t a) {
    asm volatile("ldmatrix.sync.aligned.m8n8.x4.shared.b16 {%0,%1,%2,%3}, [%4];"
        : "=r"(r[0]), "=r"(r[1]), "=r"(r[2]), "=r"(r[3]) : "r"(a));
}
__device__ __forceinline__ void cp16(uint32_t d, const void* s) {
    asm volatile("cp.async.cg.shared.global [%0], [%1], 16;" :: "r"(d), "l"(s));
}
__device__ __forceinline__ void mma16816h(float* d, const uint32_t* a,
                                          const uint32_t* b) {
    asm volatile("mma.sync.aligned.m16n8k16.row.col.f32.f16.f16.f32 "
        "{%0,%1,%2,%3}, {%4,%5,%6,%7}, {%8,%9}, {%0,%1,%2,%3};"
        : "+f"(d[0]), "+f"(d[1]), "+f"(d[2]), "+f"(d[3])
        : "r"(a[0]), "r"(a[1]), "r"(a[2]), "r"(a[3]), "r"(b[0]), "r"(b[1]));
}

// ---------------------------------------------------------------- W -> fp16
__global__ void snn_wh(const float* __restrict__ W)
{
    int idx = blockIdx.x * blockDim.x + threadIdx.x;
    if (idx >= O_ * I_) return;
    g_Wh[idx] = __float2half_rn(W[idx]);
}

// ---------------------------------------------------------------- mma GEMM
// C[128,128] per CTA, single fp16 term. 8 warps (2x4), warp tile 64x32.
// At legacy-HMMA issue floor; staging hidden by occ=2.
__global__ __launch_bounds__(256, 2)
void snn_gemm_mma(const float* __restrict__ A)
{
    extern __shared__ char smem[];
    const uint32_t sb = smem_u32(smem);
    const int tid  = threadIdx.x;
    const int lane = tid & 31;
    const int wid  = tid >> 5;
    const int wm   = wid >> 2;                  // 0..1  (M warps)
    const int wn   = wid & 3;                   // 0..3  (N warps)
    const int m0   = blockIdx.y * BM;
    const int n0   = blockIdx.x * BN;

    // A staging: thread owns row = tid>>1, k-half = (tid&1)*32
    const int arow = tid >> 1;
    const int akh  = (tid & 1) * 32;
    const float* Ap = A + (size_t)(m0 + arow) * I_ + akh;
    char* a_p = smem + SM_A + arow * LDROW + akh * 2;

    // ldmatrix per-lane coords
    const int a_r = wm * 64 + (lane & 15);
    const int a_c = (lane >> 4) * 8;
    const int b_r = wn * 32 + (lane & 15);
    const int b_c = (lane >> 4) * 8;

    float acc[4][4][4];
    #pragma unroll
    for (int mb = 0; mb < 4; mb++)
        #pragma unroll
        for (int j = 0; j < 4; j++)
            #pragma unroll
            for (int q = 0; q < 4; q++) acc[mb][j][q] = 0.0f;

    #pragma unroll 1
    for (int chunk = 0; chunk < NCHUNK; chunk++) {
        // ---- cp.async W chunk (fp16), 128 rows x 64 fp16
        #pragma unroll
        for (int i = 0; i < 4; i++) {
            int idx = tid + i * 256;
            int row = idx >> 3, c = idx & 7;
            uint32_t doff = (uint32_t)row * LDROW + c * 16;
            size_t soff = (size_t)(n0 + row) * I_ + chunk * BKC + c * 8;
            cp16(sb + SM_W + doff, g_Wh + soff);
        }
        asm volatile("cp.async.commit_group;" ::: "memory");

        // ---- A: LDG -> fp16 -> STS, two halves of 4 float4 (low reg pressure)
        const float4* Ac = (const float4*)(Ap + chunk * BKC);
        #pragma unroll
        for (int half = 0; half < 2; half++) {
            float4 v[4];
            #pragma unroll
            for (int i = 0; i < 4; i++) v[i] = Ac[half * 4 + i];
            #pragma unroll
            for (int i = 0; i < 4; i++) {
                __half2 h01 = __floats2half2_rn(v[i].x, v[i].y);
                __half2 h23 = __floats2half2_rn(v[i].z, v[i].w);
                *(uint2*)(a_p + (half * 4 + i) * 8) =
                    make_uint2(*(uint32_t*)&h01, *(uint32_t*)&h23);
            }
        }

        asm volatile("cp.async.wait_group 0;" ::: "memory");
        __syncthreads();

        // ---- compute 4 k16 steps
        #pragma unroll
        for (int ks = 0; ks < 4; ks++) {
            const int kb = ks * 16;
            uint32_t bfr[4][2];
            #pragma unroll
            for (int g = 0; g < 2; g++) {
                uint32_t rb = sb + SM_W
                            + (uint32_t)(b_r + g * 16) * LDROW + (kb + b_c) * 2;
                uint32_t r[4];
                ldsm4(r, rb);
                bfr[g*2][0] = r[0]; bfr[g*2][1] = r[2];
                bfr[g*2+1][0] = r[1]; bfr[g*2+1][1] = r[3];
            }
            #pragma unroll
            for (int mb = 0; mb < 4; mb++) {
                uint32_t afr[4];
                uint32_t ra = sb + SM_A
                            + (uint32_t)(a_r + mb * 16) * LDROW + (kb + a_c) * 2;
                ldsm4(afr, ra);
                #pragma unroll
                for (int j = 0; j < 4; j++)
                    mma16816h(acc[mb][j], afr, bfr[j]);
            }
        }
        __syncthreads();
    }

    // ---- epilogue: fragment -> g_h
    #pragma unroll
    for (int mb = 0; mb < 4; mb++) {
        int row = m0 + wm * 64 + mb * 16 + (lane >> 2);
        #pragma unroll
        for (int j = 0; j < 4; j++) {
            int col = n0 + wn * 32 + j * 8 + (lane & 3) * 2;
            float* p = g_h + (size_t)row * O_ + col;
            *(float2*)p            = make_float2(acc[mb][j][0], acc[mb][j][1]);
            *(float2*)(p + 8 * O_) = make_float2(acc[mb][j][2], acc[mb][j][3]);
        }
    }
}

// ---------------------------------------------------------------- parallel scan
// float2 chains, 10 chunks of 100, explicit 10-deep load batching (MLP=10).
// Block = 32 pairs x 10 chunks = 320 threads; grid = 256 blocks.
__global__ __launch_bounds__(320)
void snn_scan2(float* __restrict__ Y)
{
    __shared__ float2 ef[SC_C][32], eo[SC_C][32];
    __shared__ float2 qf[SC_C][32], qo[SC_C][32];

    const int tid = threadIdx.x;
    const int ch  = tid & 31;             // o-pair lane
    const int c   = tid >> 5;             // chunk 0..9
    const int pr  = blockIdx.x * 32 + ch; // global pair id, 0..8191
    const int b   = pr >> 7;              // 128 pairs per batch
    const int o   = (pr & 127) * 2;

    const float2* hp = (const float2*)
        (g_h + ((size_t)b * T_ + (size_t)c * SC_L) * O_ + o);
    const int strd = O_ / 2;              // float2 stride per t

    float2 f = make_float2(0.f, 0.f), u = make_float2(0.f, 0.f);
    #pragma unroll 1
    for (int blk = 0; blk < SC_L / SC_B; blk++) {
        float2 hb[SC_B];
        #pragma unroll
        for (int i = 0; i < SC_B; i++)
            hb[i] = hp[(size_t)(blk * SC_B + i) * strd];
        #pragma unroll
        for (int i = 0; i < SC_B; i++) {
            float2 nu = make_float2(fmaf(BETA, u.x, f.x), fmaf(BETA, u.y, f.y));
            f.x = fmaf(ALPHA, f.x, hb[i].x);
            f.y = fmaf(ALPHA, f.y, hb[i].y);
            u = nu;
        }
    }
    ef[c][ch] = f;
    eo[c][ch] = u;
    __syncthreads();

    if (tid < 32) {
        float AL = 1.0f, BL = 1.0f;
        #pragma unroll
        for (int i = 0; i < SC_L; i++) { AL *= ALPHA; BL *= BETA; }
        const float GL = (AL - BL) * (1.0f / (ALPHA - BETA));
        float2 sf = make_float2(0.f, 0.f), su = make_float2(0.f, 0.f);
        #pragma unroll
        for (int cc = 0; cc < SC_C; cc++) {
            qf[cc][tid] = sf;
            qo[cc][tid] = su;
            float2 e = ef[cc][tid], w = eo[cc][tid];
            float2 nsf = make_float2(fmaf(AL, sf.x, e.x), fmaf(AL, sf.y, e.y));
            float2 nsu = make_float2(fmaf(GL, sf.x, fmaf(BL, su.x, w.x)),
                                     fmaf(GL, sf.y, fmaf(BL, su.y, w.y)));
            sf = nsf;
            su = nsu;
        }
    }
    __syncthreads();

    f = qf[c][ch];
    u = qo[c][ch];
    float2* yp = (float2*)(Y + ((size_t)b * T_ + (size_t)c * SC_L) * O_ + o);
    #pragma unroll 1
    for (int blk = 0; blk < SC_L / SC_B; blk++) {
        float2 hb[SC_B];
        #pragma unroll
        for (int i = 0; i < SC_B; i++)
            hb[i] = hp[(size_t)(blk * SC_B + i) * strd];
        #pragma unroll
        for (int i = 0; i < SC_B; i++) {
            float2 nu = make_float2(fmaf(BETA, u.x, f.x), fmaf(BETA, u.y, f.y));
            f.x = fmaf(ALPHA, f.x, hb[i].x);
            f.y = fmaf(ALPHA, f.y, hb[i].y);
            u = nu;
            yp[(size_t)(blk * SC_B + i) * strd] = nu;
        }
    }
}

// ----------------------------------------------------------------
extern "C" void kernel_launch(void* const* d_in, const int* in_sizes, int n_in,
                              void* d_out, int out_size)
{
    const float* inputs = (const float*)d_in[0];   // (B,T,I) fp32
    const float* W      = (const float*)d_in[1];   // (O,I)   fp32
    float* out          = (float*)d_out;           // (B,T,O) fp32

    cudaFuncSetAttribute(snn_gemm_mma,
                         cudaFuncAttributeMaxDynamicSharedMemorySize, SM_GTOT);

    snn_wh<<<(O_ * I_ + 255) / 256, 256>>>(W);
    dim3 ggrid(O_ / BN, M_ / BM);                  // (2, 500)
    snn_gemm_mma<<<ggrid, 256, SM_GTOT>>>(inputs);
    snn_scan2<<<(B_ * O_ / 2) / 32, 320>>>(out);   // 256 blocks x 320 thr
}

// round 14
// speedup vs baseline: 2.1883x; 1.0718x over previous
#include <cuda_runtime.h>
#include <cuda_fp16.h>
#include <cstdint>

// ---------------------------------------------------------------- constants
#define B_   64
#define T_   1000
#define I_   512
#define O_   256
#define M_   (B_ * T_)          // 64000
#define ALPHA 0.95f
#define BETA  0.9f

// GEMM tiling
#define BM      128
#define BN      128
#define BKC     64              // K per chunk
#define NCHUNK  (I_ / BKC)      // 8
#define LDROW   144             // padded row stride in bytes (72 fp16)

// Scan chunking
#define SC_C    10
#define SC_L    (T_ / SC_C)     // 100
#define SC_B    10              // load batch depth (forced MLP)

// SMEM layout (bytes): 2 tiles of 128 rows x 144B
#define SM_A    0
#define SM_W    18432
#define SM_GTOT 36864

// ---------------------------------------------------------------- scratch
__device__ __half g_h[(size_t)M_ * O_];                 // GEMM output (fp16)
__device__ __half g_Wh[(size_t)O_ * I_];                // W fp16 (row-major [O][I])

// ---------------------------------------------------------------- helpers
__device__ __forceinline__ uint32_t smem_u32(const void* p) {
    uint32_t a;
    asm("{ .reg .u64 t; cvta.to.shared.u64 t, %1; cvt.u32.u64 %0, t; }"
        : "=r"(a) : "l"(p));
    return a;
}
__device__ __forceinline__ void ldsm4(uint32_t* r, uint32_t a) {
    asm volatile("ldmatrix.sync.aligned.m8n8.x4.shared.b16 {%0,%1,%2,%3}, [%4];"
        : "=r"(r[0]), "=r"(r[1]), "=r"(r[2]), "=r"(r[3]) : "r"(a));
}
__device__ __forceinline__ void cp16(uint32_t d, const void* s) {
    asm volatile("cp.async.cg.shared.global [%0], [%1], 16;" :: "r"(d), "l"(s));
}
__device__ __forceinline__ void mma16816h(float* d, const uint32_t* a,
                                          const uint32_t* b) {
    asm volatile("mma.sync.aligned.m16n8k16.row.col.f32.f16.f16.f32 "
        "{%0,%1,%2,%3}, {%4,%5,%6,%7}, {%8,%9}, {%0,%1,%2,%3};"
        : "+f"(d[0]), "+f"(d[1]), "+f"(d[2]), "+f"(d[3])
        : "r"(a[0]), "r"(a[1]), "r"(a[2]), "r"(a[3]), "r"(b[0]), "r"(b[1]));
}

// ---------------------------------------------------------------- W -> fp16 (vectorized)
__global__ void snn_wh(const float* __restrict__ W)
{
    int idx = blockIdx.x * blockDim.x + threadIdx.x;    // float4 index
    if (idx >= (O_ * I_) / 4) return;
    float4 v = ((const float4*)W)[idx];
    __half2 h01 = __floats2half2_rn(v.x, v.y);
    __half2 h23 = __floats2half2_rn(v.z, v.w);
    ((uint2*)g_Wh)[idx] = make_uint2(*(uint32_t*)&h01, *(uint32_t*)&h23);
}

// ---------------------------------------------------------------- mma GEMM
// C[128,128] per CTA, single fp16 term, h stored fp16.
// Mainloop is at legacy-HMMA issue floor (rt~32/SMSP) — unchanged from R12.
__global__ __launch_bounds__(256, 2)
void snn_gemm_mma(const float* __restrict__ A)
{
    extern __shared__ char smem[];
    const uint32_t sb = smem_u32(smem);
    const int tid  = threadIdx.x;
    const int lane = tid & 31;
    const int wid  = tid >> 5;
    const int wm   = wid >> 2;                  // 0..1  (M warps)
    const int wn   = wid & 3;                   // 0..3  (N warps)
    const int m0   = blockIdx.y * BM;
    const int n0   = blockIdx.x * BN;

    // A staging: thread owns row = tid>>1, k-half = (tid&1)*32
    const int arow = tid >> 1;
    const int akh  = (tid & 1) * 32;
    const float* Ap = A + (size_t)(m0 + arow) * I_ + akh;
    char* a_p = smem + SM_A + arow * LDROW + akh * 2;

    // ldmatrix per-lane coords
    const int a_r = wm * 64 + (lane & 15);
    const int a_c = (lane >> 4) * 8;
    const int b_r = wn * 32 + (lane & 15);
    const int b_c = (lane >> 4) * 8;

    float acc[4][4][4];
    #pragma unroll
    for (int mb = 0; mb < 4; mb++)
        #pragma unroll
        for (int j = 0; j < 4; j++)
            #pragma unroll
            for (int q = 0; q < 4; q++) acc[mb][j][q] = 0.0f;

    #pragma unroll 1
    for (int chunk = 0; chunk < NCHUNK; chunk++) {
        // ---- cp.async W chunk (fp16), 128 rows x 64 fp16
        #pragma unroll
        for (int i = 0; i < 4; i++) {
            int idx = tid + i * 256;
            int row = idx >> 3, c = idx & 7;
            uint32_t doff = (uint32_t)row * LDROW + c * 16;
            size_t soff = (size_t)(n0 + row) * I_ + chunk * BKC + c * 8;
            cp16(sb + SM_W + doff, g_Wh + soff);
        }
        asm volatile("cp.async.commit_group;" ::: "memory");

        // ---- A: LDG -> fp16 -> STS, two halves of 4 float4
        const float4* Ac = (const float4*)(Ap + chunk * BKC);
        #pragma unroll
        for (int half = 0; half < 2; half++) {
            float4 v[4];
            #pragma unroll
            for (int i = 0; i < 4; i++) v[i] = Ac[half * 4 + i];
            #pragma unroll
            for (int i = 0; i < 4; i++) {
                __half2 h01 = __floats2half2_rn(v[i].x, v[i].y);
                __half2 h23 = __floats2half2_rn(v[i].z, v[i].w);
                *(uint2*)(a_p + (half * 4 + i) * 8) =
                    make_uint2(*(uint32_t*)&h01, *(uint32_t*)&h23);
            }
        }

        asm volatile("cp.async.wait_group 0;" ::: "memory");
        __syncthreads();

        // ---- compute 4 k16 steps
        #pragma unroll
        for (int ks = 0; ks < 4; ks++) {
            const int kb = ks * 16;
            uint32_t bfr[4][2];
            #pragma unroll
            for (int g = 0; g < 2; g++) {
                uint32_t rb = sb + SM_W
                            + (uint32_t)(b_r + g * 16) * LDROW + (kb + b_c) * 2;
                uint32_t r[4];
                ldsm4(r, rb);
                bfr[g*2][0] = r[0]; bfr[g*2][1] = r[2];
                bfr[g*2+1][0] = r[1]; bfr[g*2+1][1] = r[3];
            }
            #pragma unroll
            for (int mb = 0; mb < 4; mb++) {
                uint32_t afr[4];
                uint32_t ra = sb + SM_A
                            + (uint32_t)(a_r + mb * 16) * LDROW + (kb + a_c) * 2;
                ldsm4(afr, ra);
                #pragma unroll
                for (int j = 0; j < 4; j++)
                    mma16816h(acc[mb][j], afr, bfr[j]);
            }
        }
        __syncthreads();
    }

    // ---- epilogue: fragment -> g_h (fp16 half2 stores)
    #pragma unroll
    for (int mb = 0; mb < 4; mb++) {
        int row = m0 + wm * 64 + mb * 16 + (lane >> 2);
        #pragma unroll
        for (int j = 0; j < 4; j++) {
            int col = n0 + wn * 32 + j * 8 + (lane & 3) * 2;
            __half* p = g_h + (size_t)row * O_ + col;
            __half2 lo = __floats2half2_rn(acc[mb][j][0], acc[mb][j][1]);
            __half2 hi = __floats2half2_rn(acc[mb][j][2], acc[mb][j][3]);
            *(__half2*)p            = lo;
            *(__half2*)(p + 8 * O_) = hi;
        }
    }
}

// ---------------------------------------------------------------- parallel scan
// half2 h chains, fp32 math, 10 chunks of 100, 10-deep load batching.
// Block = 32 pairs x 10 chunks = 320 threads; grid = 256 blocks.
__global__ __launch_bounds__(320)
void snn_scan2(float* __restrict__ Y)
{
    __shared__ float2 ef[SC_C][32], eo[SC_C][32];
    __shared__ float2 qf[SC_C][32], qo[SC_C][32];

    const int tid = threadIdx.x;
    const int ch  = tid & 31;             // o-pair lane
    const int c   = tid >> 5;             // chunk 0..9
    const int pr  = blockIdx.x * 32 + ch; // global pair id, 0..8191
    const int b   = pr >> 7;              // 128 pairs per batch
    const int o   = (pr & 127) * 2;

    const __half2* hp = (const __half2*)
        (g_h + ((size_t)b * T_ + (size_t)c * SC_L) * O_ + o);
    const int strd = O_ / 2;              // half2 stride per t

    float2 f = make_float2(0.f, 0.f), u = make_float2(0.f, 0.f);
    #pragma unroll 1
    for (int blk = 0; blk < SC_L / SC_B; blk++) {
        __half2 hb[SC_B];
        #pragma unroll
        for (int i = 0; i < SC_B; i++)
            hb[i] = hp[(size_t)(blk * SC_B + i) * strd];
        #pragma unroll
        for (int i = 0; i < SC_B; i++) {
            float2 h  = __half22float2(hb[i]);
            float2 nu = make_float2(fmaf(BETA, u.x, f.x), fmaf(BETA, u.y, f.y));
            f.x = fmaf(ALPHA, f.x, h.x);
            f.y = fmaf(ALPHA, f.y, h.y);
            u = nu;
        }
    }
    ef[c][ch] = f;
    eo[c][ch] = u;
    __syncthreads();

    if (tid < 32) {
        float AL = 1.0f, BL = 1.0f;
        #pragma unroll
        for (int i = 0; i < SC_L; i++) { AL *= ALPHA; BL *= BETA; }
        const float GL = (AL - BL) * (1.0f / (ALPHA - BETA));
        float2 sf = make_float2(0.f, 0.f), su = make_float2(0.f, 0.f);
        #pragma unroll
        for (int cc = 0; cc < SC_C; cc++) {
            qf[cc][tid] = sf;
            qo[cc][tid] = su;
            float2 e = ef[cc][tid], w = eo[cc][tid];
            float2 nsf = make_float2(fmaf(AL, sf.x, e.x), fmaf(AL, sf.y, e.y));
            float2 nsu = make_float2(fmaf(GL, sf.x, fmaf(BL, su.x, w.x)),
                                     fmaf(GL, sf.y, fmaf(BL, su.y, w.y)));
            sf = nsf;
            su = nsu;
        }
    }
    __syncthreads();

    f = qf[c][ch];
    u = qo[c][ch];
    float2* yp = (float2*)(Y + ((size_t)b * T_ + (size_t)c * SC_L) * O_ + o);
    #pragma unroll 1
    for (int blk = 0; blk < SC_L / SC_B; blk++) {
        __half2 hb[SC_B];
        #pragma unroll
        for (int i = 0; i < SC_B; i++)
            hb[i] = hp[(size_t)(blk * SC_B + i) * strd];
        #pragma unroll
        for (int i = 0; i < SC_B; i++) {
            float2 h  = __half22float2(hb[i]);
            float2 nu = make_float2(fmaf(BETA, u.x, f.x), fmaf(BETA, u.y, f.y));
            f.x = fmaf(ALPHA, f.x, h.x);
            f.y = fmaf(ALPHA, f.y, h.y);
            u = nu;
            yp[(size_t)(blk * SC_B + i) * strd] = nu;
        }
    }
}

// ----------------------------------------------------------------
extern "C" void kernel_launch(void* const* d_in, const int* in_sizes, int n_in,
                              void* d_out, int out_size)
{
    const float* inputs = (const float*)d_in[0];   // (B,T,I) fp32
    const float* W      = (const float*)d_in[1];   // (O,I)   fp32
    float* out          = (float*)d_out;           // (B,T,O) fp32

    cudaFuncSetAttribute(snn_gemm_mma,
                         cudaFuncAttributeMaxDynamicSharedMemorySize, SM_GTOT);

    snn_wh<<<(O_ * I_ / 4 + 255) / 256, 256>>>(W); // 128 blocks, float4
    dim3 ggrid(O_ / BN, M_ / BM);                  // (2, 500)
    snn_gemm_mma<<<ggrid, 256, SM_GTOT>>>(inputs);
    snn_scan2<<<(B_ * O_ / 2) / 32, 320>>>(out);   // 256 blocks x 320 thr
}

// round 15
// speedup vs baseline: 2.2110x; 1.0104x over previous
#include <cuda_runtime.h>
#include <cuda_fp16.h>
#include <cstdint>

// ---------------------------------------------------------------- constants
#define B_   64
#define T_   1000
#define I_   512
#define O_   256
#define M_   (B_ * T_)          // 64000
#define ALPHA 0.95f
#define BETA  0.9f

// GEMM tiling
#define BM      128
#define BN      128
#define BKC     64              // K per chunk
#define NCHUNK  (I_ / BKC)      // 8
#define LDROW   144             // padded row stride in bytes (72 fp16)

// Scan chunking
#define SC_C    20
#define SC_L    (T_ / SC_C)     // 50
#define SC_B    10              // load batch depth (forced MLP)

// SMEM layout (bytes): 2 tiles of 128 rows x 144B
#define SM_A    0
#define SM_W    18432
#define SM_GTOT 36864

// ---------------------------------------------------------------- scratch
__device__ __half g_h[(size_t)M_ * O_];                 // GEMM output (fp16)
__device__ __half g_Wh[(size_t)O_ * I_];                // W fp16 (row-major [O][I])

// ---------------------------------------------------------------- helpers
__device__ __forceinline__ uint32_t smem_u32(const void* p) {
    uint32_t a;
    asm("{ .reg .u64 t; cvta.to.shared.u64 t, %1; cvt.u32.u64 %0, t; }"
        : "=r"(a) : "l"(p));
    return a;
}
__device__ __forceinline__ void ldsm4(uint32_t* r, uint32_t a) {
    asm volatile("ldmatrix.sync.aligned.m8n8.x4.shared.b16 {%0,%1,%2,%3}, [%4];"
        : "=r"(r[0]), "=r"(r[1]), "=r"(r[2]), "=r"(r[3]) : "r"(a));
}
__device__ __forceinline__ void cp16(uint32_t d, const void* s) {
    asm volatile("cp.async.cg.shared.global [%0], [%1], 16;" :: "r"(d), "l"(s));
}
__device__ __forceinline__ void mma16816h(float* d, const uint32_t* a,
                                          const uint32_t* b) {
    asm volatile("mma.sync.aligned.m16n8k16.row.col.f32.f16.f16.f32 "
        "{%0,%1,%2,%3}, {%4,%5,%6,%7}, {%8,%9}, {%0,%1,%2,%3};"
        : "+f"(d[0]), "+f"(d[1]), "+f"(d[2]), "+f"(d[3])
        : "r"(a[0]), "r"(a[1]), "r"(a[2]), "r"(a[3]), "r"(b[0]), "r"(b[1]));
}

// ---------------------------------------------------------------- W -> fp16
__global__ void snn_wh(const float* __restrict__ W)
{
    int idx = blockIdx.x * blockDim.x + threadIdx.x;    // float4 index
    if (idx >= (O_ * I_) / 4) return;
    float4 v = ((const float4*)W)[idx];
    __half2 h01 = __floats2half2_rn(v.x, v.y);
    __half2 h23 = __floats2half2_rn(v.z, v.w);
    ((uint2*)g_Wh)[idx] = make_uint2(*(uint32_t*)&h01, *(uint32_t*)&h23);
}

// ---------------------------------------------------------------- mma GEMM
// C[128,128] per CTA, single fp16 term, h stored fp16.
// At legacy-HMMA issue floor (rt~32/SMSP) — frozen since R12.
__global__ __launch_bounds__(256, 2)
void snn_gemm_mma(const float* __restrict__ A)
{
    extern __shared__ char smem[];
    const uint32_t sb = smem_u32(smem);
    const int tid  = threadIdx.x;
    const int lane = tid & 31;
    const int wid  = tid >> 5;
    const int wm   = wid >> 2;                  // 0..1  (M warps)
    const int wn   = wid & 3;                   // 0..3  (N warps)
    const int m0   = blockIdx.y * BM;
    const int n0   = blockIdx.x * BN;

    // A staging: thread owns row = tid>>1, k-half = (tid&1)*32
    const int arow = tid >> 1;
    const int akh  = (tid & 1) * 32;
    const float* Ap = A + (size_t)(m0 + arow) * I_ + akh;
    char* a_p = smem + SM_A + arow * LDROW + akh * 2;

    // ldmatrix per-lane coords
    const int a_r = wm * 64 + (lane & 15);
    const int a_c = (lane >> 4) * 8;
    const int b_r = wn * 32 + (lane & 15);
    const int b_c = (lane >> 4) * 8;

    float acc[4][4][4];
    #pragma unroll
    for (int mb = 0; mb < 4; mb++)
        #pragma unroll
        for (int j = 0; j < 4; j++)
            #pragma unroll
            for (int q = 0; q < 4; q++) acc[mb][j][q] = 0.0f;

    #pragma unroll 1
    for (int chunk = 0; chunk < NCHUNK; chunk++) {
        // ---- cp.async W chunk (fp16), 128 rows x 64 fp16
        #pragma unroll
        for (int i = 0; i < 4; i++) {
            int idx = tid + i * 256;
            int row = idx >> 3, c = idx & 7;
            uint32_t doff = (uint32_t)row * LDROW + c * 16;
            size_t soff = (size_t)(n0 + row) * I_ + chunk * BKC + c * 8;
            cp16(sb + SM_W + doff, g_Wh + soff);
        }
        asm volatile("cp.async.commit_group;" ::: "memory");

        // ---- A: LDG -> fp16 -> STS, two halves of 4 float4
        const float4* Ac = (const float4*)(Ap + chunk * BKC);
        #pragma unroll
        for (int half = 0; half < 2; half++) {
            float4 v[4];
            #pragma unroll
            for (int i = 0; i < 4; i++) v[i] = Ac[half * 4 + i];
            #pragma unroll
            for (int i = 0; i < 4; i++) {
                __half2 h01 = __floats2half2_rn(v[i].x, v[i].y);
                __half2 h23 = __floats2half2_rn(v[i].z, v[i].w);
                *(uint2*)(a_p + (half * 4 + i) * 8) =
                    make_uint2(*(uint32_t*)&h01, *(uint32_t*)&h23);
            }
        }

        asm volatile("cp.async.wait_group 0;" ::: "memory");
        __syncthreads();

        // ---- compute 4 k16 steps
        #pragma unroll
        for (int ks = 0; ks < 4; ks++) {
            const int kb = ks * 16;
            uint32_t bfr[4][2];
            #pragma unroll
            for (int g = 0; g < 2; g++) {
                uint32_t rb = sb + SM_W
                            + (uint32_t)(b_r + g * 16) * LDROW + (kb + b_c) * 2;
                uint32_t r[4];
                ldsm4(r, rb);
                bfr[g*2][0] = r[0]; bfr[g*2][1] = r[2];
                bfr[g*2+1][0] = r[1]; bfr[g*2+1][1] = r[3];
            }
            #pragma unroll
            for (int mb = 0; mb < 4; mb++) {
                uint32_t afr[4];
                uint32_t ra = sb + SM_A
                            + (uint32_t)(a_r + mb * 16) * LDROW + (kb + a_c) * 2;
                ldsm4(afr, ra);
                #pragma unroll
                for (int j = 0; j < 4; j++)
                    mma16816h(acc[mb][j], afr, bfr[j]);
            }
        }
        __syncthreads();
    }

    // ---- epilogue: fragment -> g_h (fp16 half2 stores)
    #pragma unroll
    for (int mb = 0; mb < 4; mb++) {
        int row = m0 + wm * 64 + mb * 16 + (lane >> 2);
        #pragma unroll
        for (int j = 0; j < 4; j++) {
            int col = n0 + wn * 32 + j * 8 + (lane & 3) * 2;
            __half* p = g_h + (size_t)row * O_ + col;
            __half2 lo = __floats2half2_rn(acc[mb][j][0], acc[mb][j][1]);
            __half2 hi = __floats2half2_rn(acc[mb][j][2], acc[mb][j][3]);
            *(__half2*)p            = lo;
            *(__half2*)(p + 8 * O_) = hi;
        }
    }
}

// ---------------------------------------------------------------- parallel scan
// half2 h chains, fp32 math, 20 chunks of 50, 10-deep load batching.
// Block = 32 pairs x 20 chunks = 640 threads; grid = 256 blocks.
__global__ __launch_bounds__(640)
void snn_scan2(float* __restrict__ Y)
{
    __shared__ float2 ef[SC_C][32], eo[SC_C][32];
    __shared__ float2 qf[SC_C][32], qo[SC_C][32];

    const int tid = threadIdx.x;
    const int ch  = tid & 31;             // o-pair lane
    const int c   = tid >> 5;             // chunk 0..19
    const int pr  = blockIdx.x * 32 + ch; // global pair id, 0..8191
    const int b   = pr >> 7;              // 128 pairs per batch
    const int o   = (pr & 127) * 2;

    const __half2* hp = (const __half2*)
        (g_h + ((size_t)b * T_ + (size_t)c * SC_L) * O_ + o);
    const int strd = O_ / 2;              // half2 stride per t

    float2 f = make_float2(0.f, 0.f), u = make_float2(0.f, 0.f);
    #pragma unroll 1
    for (int blk = 0; blk < SC_L / SC_B; blk++) {
        __half2 hb[SC_B];
        #pragma unroll
        for (int i = 0; i < SC_B; i++)
            hb[i] = hp[(size_t)(blk * SC_B + i) * strd];
        #pragma unroll
        for (int i = 0; i < SC_B; i++) {
            float2 h  = __half22float2(hb[i]);
            float2 nu = make_float2(fmaf(BETA, u.x, f.x), fmaf(BETA, u.y, f.y));
            f.x = fmaf(ALPHA, f.x, h.x);
            f.y = fmaf(ALPHA, f.y, h.y);
            u = nu;
        }
    }
    ef[c][ch] = f;
    eo[c][ch] = u;
    __syncthreads();

    if (tid < 32) {
        float AL = 1.0f, BL = 1.0f;
        #pragma unroll
        for (int i = 0; i < SC_L; i++) { AL *= ALPHA; BL *= BETA; }
        const float GL = (AL - BL) * (1.0f / (ALPHA - BETA));
        float2 sf = make_float2(0.f, 0.f), su = make_float2(0.f, 0.f);
        #pragma unroll
        for (int cc = 0; cc < SC_C; cc++) {
            qf[cc][tid] = sf;
            qo[cc][tid] = su;
            float2 e = ef[cc][tid], w = eo[cc][tid];
            float2 nsf = make_float2(fmaf(AL, sf.x, e.x), fmaf(AL, sf.y, e.y));
            float2 nsu = make_float2(fmaf(GL, sf.x, fmaf(BL, su.x, w.x)),
                                     fmaf(GL, sf.y, fmaf(BL, su.y, w.y)));
            sf = nsf;
            su = nsu;
        }
    }
    __syncthreads();

    f = qf[c][ch];
    u = qo[c][ch];
    float2* yp = (float2*)(Y + ((size_t)b * T_ + (size_t)c * SC_L) * O_ + o);
    #pragma unroll 1
    for (int blk = 0; blk < SC_L / SC_B; blk++) {
        __half2 hb[SC_B];
        #pragma unroll
        for (int i = 0; i < SC_B; i++)
            hb[i] = hp[(size_t)(blk * SC_B + i) * strd];
        #pragma unroll
        for (int i = 0; i < SC_B; i++) {
            float2 h  = __half22float2(hb[i]);
            float2 nu = make_float2(fmaf(BETA, u.x, f.x), fmaf(BETA, u.y, f.y));
            f.x = fmaf(ALPHA, f.x, h.x);
            f.y = fmaf(ALPHA, f.y, h.y);
            u = nu;
            yp[(size_t)(blk * SC_B + i) * strd] = nu;
        }
    }
}

// ----------------------------------------------------------------
extern "C" void kernel_launch(void* const* d_in, const int* in_sizes, int n_in,
                              void* d_out, int out_size)
{
    const float* inputs = (const float*)d_in[0];   // (B,T,I) fp32
    const float* W      = (const float*)d_in[1];   // (O,I)   fp32
    float* out          = (float*)d_out;           // (B,T,O) fp32

    cudaFuncSetAttribute(snn_gemm_mma,
                         cudaFuncAttributeMaxDynamicSharedMemorySize, SM_GTOT);

    snn_wh<<<(O_ * I_ / 4 + 255) / 256, 256>>>(W); // 128 blocks, float4
    dim3 ggrid(O_ / BN, M_ / BM);                  // (2, 500)
    snn_gemm_mma<<<ggrid, 256, SM_GTOT>>>(inputs);
    snn_scan2<<<(B_ * O_ / 2) / 32, 640>>>(out);   // 256 blocks x 640 thr
}